// round 16
// baseline (speedup 1.0000x reference)
#include <cuda_runtime.h>
#include <cuda_bf16.h>
#include <cuda_fp16.h>
#include <math.h>
#include <stdint.h>

#define NN 50000
#define EE 1600000
#define HH 128
#define DIN 64
#define DE 16
#define LL 6

// ---------------- scratch (static __device__ globals; no allocation) ----------------
__device__ float g_ha[NN * HH];     // node features (always post-relu)
__device__ __half g_msgh[NN * HH];  // per-node message linear output (fp16)
__device__ float g_a2[NN * HH];     // ha + agg (input to update GEMM)
__device__ float g_ssrc[NN];
__device__ float g_sdst[NN];
// per-layer per-edge record in CSR order: {src, ew(bits), s_bias(bits), 0}
__device__ uint4 g_epack[(size_t)LL * EE];
__device__ int g_counts[NN];
__device__ int g_rowptr[NN + 1];
__device__ int g_cursor[NN];
__device__ int g_perm[EE];   // csr pos -> original edge id
__device__ int g_srcp[EE];   // csr-ordered src index
__device__ float g_ewp[EE];  // csr-ordered clipped edge weight
__device__ float g_w1p[LL * HH * DE];  // W_e1 * colsum(W_e2)  (SIGNED fold)
__device__ float g_b1p[LL * HH];       // b_e1 * colsum(W_e2)
__device__ float g_sgnF[LL * HH];      // sign(colsum(W_e2)) as +-1.0f
__device__ float g_cas[LL * HH];       // colsum(W_as)
__device__ float g_cad[LL * HH];       // colsum(W_ad)
__device__ float g_be2s[LL];
__device__ float g_bass[LL];
__device__ float g_bads[LL];
__device__ float g_gpart[256 * HH];
__device__ int g_bsum[49];
__device__ int g_boff[49];
// pre-packed B fragments for edge-MLP mma: [l][ntile][lane] -> {b0_hi, b1_hi, b0_lo, b1_lo}
__device__ __align__(16) uint4 g_Bfrag[LL * 16 * 32];
// pre-packed W fragments for node GEMMs: 12 matrices (l*2: W_m, l*2+1: W_r)
__device__ __align__(16) uint4 g_Wfrag[12 * 4096];

// ---------------- small helpers ----------------
__device__ __forceinline__ float tanh_fast(float x) {
    float y;
    asm("tanh.approx.f32 %0, %1;" : "=f"(y) : "f"(x));
    return y;
}
__device__ __forceinline__ unsigned pk2(float a, float b) {
    __nv_bfloat162 t = __floats2bfloat162_rn(a, b);
    return *reinterpret_cast<unsigned*>(&t);
}
__device__ __forceinline__ float hif(float a) {
    return __bfloat162float(__float2bfloat16(a));
}
__device__ __forceinline__ void mma16816(float& d0, float& d1, float& d2, float& d3,
                                         unsigned a0, unsigned a1, unsigned a2, unsigned a3,
                                         unsigned b0, unsigned b1,
                                         float c0, float c1, float c2, float c3) {
    asm volatile(
        "mma.sync.aligned.m16n8k16.row.col.f32.bf16.bf16.f32 "
        "{%0,%1,%2,%3}, {%4,%5,%6,%7}, {%8,%9}, {%10,%11,%12,%13};"
        : "=f"(d0), "=f"(d1), "=f"(d2), "=f"(d3)
        : "r"(a0), "r"(a1), "r"(a2), "r"(a3), "r"(b0), "r"(b1),
          "f"(c0), "f"(c1), "f"(c2), "f"(c3));
}

// ---------------- init: zero histogram counters ----------------
__global__ void k_init() {
    int i = blockIdx.x * blockDim.x + threadIdx.x;
    if (i < NN) g_counts[i] = 0;
}

// ---------------- precompute column sums / folded edge-MLP weights ----------------
__global__ void k_prep(const float* __restrict__ W_e1, const float* __restrict__ b_e1,
                       const float* __restrict__ W_e2, const float* __restrict__ b_e2,
                       const float* __restrict__ W_as, const float* __restrict__ b_as,
                       const float* __restrict__ W_ad, const float* __restrict__ b_ad) {
    int l = blockIdx.x;       // 0..5
    int t = threadIdx.x;      // 0..127
    const float* was = W_as + l * HH * HH;
    const float* wad = W_ad + l * HH * HH;
    const float* we2 = W_e2 + l * HH * HH;
    float sa = 0.f, sd = 0.f, s2 = 0.f;
    for (int j = 0; j < HH; j++) {
        sa += was[j * HH + t];
        sd += wad[j * HH + t];
        s2 += we2[j * HH + t];
    }
    g_cas[l * HH + t] = sa;
    g_cad[l * HH + t] = sd;
    g_b1p[l * HH + t] = b_e1[l * HH + t] * s2;
    g_sgnF[l * HH + t] = (s2 < 0.f) ? -1.f : 1.f;
    const float* we1 = W_e1 + (l * HH + t) * DE;
    float* w1p = g_w1p + (l * HH + t) * DE;
    for (int k = 0; k < DE; k++) w1p[k] = we1[k] * s2;
    if (t == 0) {
        float s = 0.f;
        for (int j = 0; j < HH; j++) s += b_e2[l * HH + j];
        g_be2s[l] = s;
        s = 0.f;
        for (int j = 0; j < HH; j++) s += b_as[l * HH + j];
        g_bass[l] = s;
        s = 0.f;
        for (int j = 0; j < HH; j++) s += b_ad[l * HH + j];
        g_bads[l] = s;
    }
}

// ---------------- pre-pack B fragments (edge MLP, K=16) ----------------
__global__ void k_prepB() {
    int l = blockIdx.x >> 4;
    int nt = blockIdx.x & 15;
    int lane = threadIdx.x;
    int n = nt * 8 + (lane >> 2);
    int k0 = (lane & 3) * 2;
    const float* w = g_w1p + (l * HH + n) * DE;
    float w0 = w[k0], w1 = w[k0 + 1], w8 = w[k0 + 8], w9 = w[k0 + 9];
    float h0 = hif(w0), h1 = hif(w1), h8 = hif(w8), h9 = hif(w9);
    uint4 f;
    f.x = pk2(h0, h1);
    f.y = pk2(h8, h9);
    f.z = pk2(w0 - h0, w1 - h1);
    f.w = pk2(w8 - h8, w9 - h9);
    g_Bfrag[(l * 16 + nt) * 32 + lane] = f;
}

// ---------------- pre-pack W fragments (node GEMMs, K=128) ----------------
__global__ void k_prepW(const float* __restrict__ Wm, const float* __restrict__ Wr) {
    int m = blockIdx.x >> 7;
    int rem = blockIdx.x & 127;
    int ks = rem >> 4;
    int nt = rem & 15;
    const float* W = (m & 1) ? (Wr + (m >> 1) * HH * HH) : (Wm + (m >> 1) * HH * HH);
    int lane = threadIdx.x;
    int n = nt * 8 + (lane >> 2);
    int k0 = ks * 16 + (lane & 3) * 2;
    float w0 = W[n * HH + k0], w1 = W[n * HH + k0 + 1];
    float w8 = W[n * HH + k0 + 8], w9 = W[n * HH + k0 + 9];
    float h0 = hif(w0), h1 = hif(w1), h8 = hif(w8), h9 = hif(w9);
    uint4 f;
    f.x = pk2(h0, h1);
    f.y = pk2(h8, h9);
    f.z = pk2(w0 - h0, w1 - h1);
    f.w = pk2(w8 - h8, w9 - h9);
    g_Wfrag[m * 4096 + (ks * 16 + nt) * 32 + lane] = f;
}

// ---------------- CSR build ----------------
__global__ void k_hist(const int* __restrict__ ei) {
    int e = blockIdx.x * blockDim.x + threadIdx.x;
    if (e < EE) atomicAdd(&g_counts[ei[EE + e]], 1);
}

__global__ void k_scanA() {
    __shared__ int sh[1024];
    int i = blockIdx.x * 1024 + threadIdx.x;
    int v = (i < NN) ? g_counts[i] : 0;
    sh[threadIdx.x] = v;
    __syncthreads();
    for (int off = 512; off > 0; off >>= 1) {
        if (threadIdx.x < off) sh[threadIdx.x] += sh[threadIdx.x + off];
        __syncthreads();
    }
    if (threadIdx.x == 0) g_bsum[blockIdx.x] = sh[0];
}
__global__ void k_scanB() {
    if (threadIdx.x == 0) {
        int r = 0;
        for (int b = 0; b < 49; b++) { g_boff[b] = r; r += g_bsum[b]; }
    }
}
__global__ void k_scanC() {
    __shared__ int sh[1024];
    int t = threadIdx.x;
    int i = blockIdx.x * 1024 + t;
    int v = (i < NN) ? g_counts[i] : 0;
    sh[t] = v;
    __syncthreads();
    for (int off = 1; off < 1024; off <<= 1) {
        int x = (t >= off) ? sh[t - off] : 0;
        __syncthreads();
        sh[t] += x;
        __syncthreads();
    }
    if (i < NN) {
        int excl = sh[t] - v + g_boff[blockIdx.x];
        g_rowptr[i] = excl;
        g_cursor[i] = excl;
        if (i == NN - 1) g_rowptr[NN] = excl + v;
    }
}

__global__ void k_scatter(const int* __restrict__ ei, const float* __restrict__ ew) {
    int e = blockIdx.x * blockDim.x + threadIdx.x;
    if (e >= EE) return;
    int d = ei[EE + e];
    int pos = atomicAdd(&g_cursor[d], 1);
    g_perm[pos] = e;
    g_srcp[pos] = ei[e];
    float w = ew[e];
    g_ewp[pos] = fminf(fmaxf(w, 0.f), 1.f);
}

// ---------------- per-edge bias for all 6 layers via mma.sync bf16 ----------------
// Writes packed per-layer edge records {src, ew, s_bias, 0} for k_agg.
#define SBT_SMEM (49152 + 3072 + 3072)
__global__ __launch_bounds__(256) void k_sbias_tc(const float* __restrict__ ea) {
    extern __shared__ char smem[];
    uint4* sF = reinterpret_cast<uint4*>(smem);
    float* sB = reinterpret_cast<float*>(smem + 49152);
    float* sS = reinterpret_cast<float*>(smem + 49152 + 3072);
    for (int i = threadIdx.x; i < 3072; i += 256) sF[i] = g_Bfrag[i];
    for (int i = threadIdx.x; i < 768; i += 256) {
        sB[i] = g_b1p[i];
        sS[i] = g_sgnF[i];
    }
    __syncthreads();

    const int wid = threadIdx.x >> 5;
    const int lane = threadIdx.x & 31;
    const int rA = lane >> 2;
    const int qq = lane & 3;

    for (int tile = blockIdx.x; tile < EE / 128; tile += gridDim.x) {
        const int p0 = tile * 128 + wid * 16;
        unsigned ah[4], al[4];
        {
            int e0 = g_perm[p0 + rA];
            int e1 = g_perm[p0 + rA + 8];
            const float2* r0 = reinterpret_cast<const float2*>(ea + (size_t)e0 * DE);
            const float2* r1 = reinterpret_cast<const float2*>(ea + (size_t)e1 * DE);
            float2 x0 = r0[qq], x2 = r0[qq + 4];
            float2 y0 = r1[qq], y2 = r1[qq + 4];
            x0.x = tanh_fast(x0.x); x0.y = tanh_fast(x0.y);
            x2.x = tanh_fast(x2.x); x2.y = tanh_fast(x2.y);
            y0.x = tanh_fast(y0.x); y0.y = tanh_fast(y0.y);
            y2.x = tanh_fast(y2.x); y2.y = tanh_fast(y2.y);
            float hx0 = hif(x0.x), hx1 = hif(x0.y);
            float hx8 = hif(x2.x), hx9 = hif(x2.y);
            float hy0 = hif(y0.x), hy1 = hif(y0.y);
            float hy8 = hif(y2.x), hy9 = hif(y2.y);
            ah[0] = pk2(hx0, hx1);
            ah[1] = pk2(hy0, hy1);
            ah[2] = pk2(hx8, hx9);
            ah[3] = pk2(hy8, hy9);
            al[0] = pk2(x0.x - hx0, x0.y - hx1);
            al[1] = pk2(y0.x - hy0, y0.y - hy1);
            al[2] = pk2(x2.x - hx8, x2.y - hx9);
            al[3] = pk2(y2.x - hy8, y2.y - hy9);
        }
        // per-edge src/ew for the pack (only needed on qq==0 lanes)
        unsigned eS0 = 0, eS1 = 0, eW0 = 0, eW1 = 0;
        if (qq == 0) {
            eS0 = (unsigned)g_srcp[p0 + rA];
            eS1 = (unsigned)g_srcp[p0 + rA + 8];
            eW0 = __float_as_uint(g_ewp[p0 + rA]);
            eW1 = __float_as_uint(g_ewp[p0 + rA + 8]);
        }
#pragma unroll 1
        for (int l = 0; l < LL; l++) {
            const float* bl = sB + l * HH;
            const float* sl = sS + l * HH;
            float accA = 0.f, accB = 0.f;
#pragma unroll
            for (int nt = 0; nt < 16; nt++) {
                uint4 bf = sF[(l * 16 + nt) * 32 + lane];
                float2 bb = *reinterpret_cast<const float2*>(bl + nt * 8 + qq * 2);
                float d0 = bb.x, d1 = bb.y, d2 = bb.x, d3 = bb.y;
                mma16816(d0, d1, d2, d3, ah[0], ah[1], ah[2], ah[3], bf.x, bf.y,
                         d0, d1, d2, d3);
                mma16816(d0, d1, d2, d3, al[0], al[1], al[2], al[3], bf.x, bf.y,
                         d0, d1, d2, d3);
                mma16816(d0, d1, d2, d3, ah[0], ah[1], ah[2], ah[3], bf.z, bf.w,
                         d0, d1, d2, d3);
                float2 ss = *reinterpret_cast<const float2*>(sl + nt * 8 + qq * 2);
                accA = fmaf(fmaxf(d0 * ss.x, 0.f), ss.x, accA);
                accA = fmaf(fmaxf(d1 * ss.y, 0.f), ss.y, accA);
                accB = fmaf(fmaxf(d2 * ss.x, 0.f), ss.x, accB);
                accB = fmaf(fmaxf(d3 * ss.y, 0.f), ss.y, accB);
            }
            accA += __shfl_xor_sync(0xffffffffu, accA, 1);
            accA += __shfl_xor_sync(0xffffffffu, accA, 2);
            accB += __shfl_xor_sync(0xffffffffu, accB, 1);
            accB += __shfl_xor_sync(0xffffffffu, accB, 2);
            if (qq == 0) {
                float c = g_be2s[l];
                uint4 rec0, rec1;
                rec0.x = eS0; rec0.y = eW0;
                rec0.z = __float_as_uint(accA + c); rec0.w = 0u;
                rec1.x = eS1; rec1.y = eW1;
                rec1.z = __float_as_uint(accB + c); rec1.w = 0u;
                g_epack[(size_t)l * EE + p0 + rA] = rec0;
                g_epack[(size_t)l * EE + p0 + rA + 8] = rec1;
            }
        }
    }
}

// ---------------- tensor-core node GEMM: C = act(A @ W^T + b) ----------------
// Software-pipelined A loads: next ks-step's registers are fetched before the
// MMA block so L2 latency overlaps tensor work.
#define GT_SMEM (65536 + 512 + 1024)
__global__ __launch_bounds__(256) void k_gemm_tc(int a_sel, int mat,
                                                 const float* __restrict__ bias,
                                                 int c_sel, int do_relu,
                                                 int do_scores, int l) {
    extern __shared__ char smem[];
    uint4* sW = reinterpret_cast<uint4*>(smem);
    float* sBias = reinterpret_cast<float*>(smem + 65536);
    float* sCas = reinterpret_cast<float*>(smem + 65536 + 512);
    float* sCad = sCas + 128;

    const float* A = (a_sel == 1) ? g_ha : g_a2;
    const uint4* Wf = g_Wfrag + (size_t)mat * 4096;

    for (int i = threadIdx.x; i < 4096; i += 256) sW[i] = Wf[i];
    if (threadIdx.x < 128) {
        sBias[threadIdx.x] = bias[threadIdx.x];
        if (do_scores) {
            sCas[threadIdx.x] = g_cas[l * HH + threadIdx.x];
            sCad[threadIdx.x] = g_cad[l * HH + threadIdx.x];
        }
    }
    __syncthreads();

    const int wid = threadIdx.x >> 5;
    const int lane = threadIdx.x & 31;
    const int rA = lane >> 2;
    const int qq = lane & 3;

    const int row0 = blockIdx.x * 128 + wid * 16 + rA;
    const int r0 = (row0 < NN) ? row0 : (NN - 1);
    const int r1 = (row0 + 8 < NN) ? (row0 + 8) : (NN - 1);
    const float* ar0 = A + (size_t)r0 * HH;
    const float* ar1 = A + (size_t)r1 * HH;

    float acc[16][4];
#pragma unroll
    for (int nt = 0; nt < 16; nt++)
#pragma unroll
        for (int j = 0; j < 4; j++) acc[nt][j] = 0.f;

    float vs0 = 0.f, vd0 = 0.f, vs1 = 0.f, vd1 = 0.f;

    // prologue: load ks=0
    float2 x0 = *reinterpret_cast<const float2*>(ar0 + qq * 2);
    float2 x8 = *reinterpret_cast<const float2*>(ar0 + qq * 2 + 8);
    float2 y0 = *reinterpret_cast<const float2*>(ar1 + qq * 2);
    float2 y8 = *reinterpret_cast<const float2*>(ar1 + qq * 2 + 8);

#pragma unroll 1
    for (int ks = 0; ks < 8; ks++) {
        // prefetch next ks-step BEFORE touching current values
        float2 nx0 = make_float2(0.f, 0.f), nx8 = nx0, ny0 = nx0, ny8 = nx0;
        if (ks < 7) {
            const float* br0 = ar0 + (ks + 1) * 16;
            const float* br1 = ar1 + (ks + 1) * 16;
            nx0 = *reinterpret_cast<const float2*>(br0 + qq * 2);
            nx8 = *reinterpret_cast<const float2*>(br0 + qq * 2 + 8);
            ny0 = *reinterpret_cast<const float2*>(br1 + qq * 2);
            ny8 = *reinterpret_cast<const float2*>(br1 + qq * 2 + 8);
        }
        if (do_scores) {
            int c0 = ks * 16 + qq * 2;
            vs0 += x0.x * sCas[c0] + x0.y * sCas[c0 + 1]
                 + x8.x * sCas[c0 + 8] + x8.y * sCas[c0 + 9];
            vd0 += x0.x * sCad[c0] + x0.y * sCad[c0 + 1]
                 + x8.x * sCad[c0 + 8] + x8.y * sCad[c0 + 9];
            vs1 += y0.x * sCas[c0] + y0.y * sCas[c0 + 1]
                 + y8.x * sCas[c0 + 8] + y8.y * sCas[c0 + 9];
            vd1 += y0.x * sCad[c0] + y0.y * sCad[c0 + 1]
                 + y8.x * sCad[c0 + 8] + y8.y * sCad[c0 + 9];
        }
        float hx0 = hif(x0.x), hx1 = hif(x0.y), hx8 = hif(x8.x), hx9 = hif(x8.y);
        float hy0 = hif(y0.x), hy1 = hif(y0.y), hy8 = hif(y8.x), hy9 = hif(y8.y);
        unsigned ah0 = pk2(hx0, hx1), ah1 = pk2(hy0, hy1);
        unsigned ah2 = pk2(hx8, hx9), ah3 = pk2(hy8, hy9);
        unsigned al0 = pk2(x0.x - hx0, x0.y - hx1);
        unsigned al1 = pk2(y0.x - hy0, y0.y - hy1);
        unsigned al2 = pk2(x8.x - hx8, x8.y - hx9);
        unsigned al3 = pk2(y8.x - hy8, y8.y - hy9);
        const uint4* wrow = sW + ks * 512 + lane;
#pragma unroll
        for (int nt = 0; nt < 16; nt++) {
            uint4 bf = wrow[nt * 32];
            mma16816(acc[nt][0], acc[nt][1], acc[nt][2], acc[nt][3],
                     ah0, ah1, ah2, ah3, bf.x, bf.y,
                     acc[nt][0], acc[nt][1], acc[nt][2], acc[nt][3]);
            mma16816(acc[nt][0], acc[nt][1], acc[nt][2], acc[nt][3],
                     al0, al1, al2, al3, bf.x, bf.y,
                     acc[nt][0], acc[nt][1], acc[nt][2], acc[nt][3]);
            mma16816(acc[nt][0], acc[nt][1], acc[nt][2], acc[nt][3],
                     ah0, ah1, ah2, ah3, bf.z, bf.w,
                     acc[nt][0], acc[nt][1], acc[nt][2], acc[nt][3]);
        }
        x0 = nx0; x8 = nx8; y0 = ny0; y8 = ny8;
    }

    if (do_scores) {
        vs0 += __shfl_xor_sync(0xffffffffu, vs0, 1);
        vs0 += __shfl_xor_sync(0xffffffffu, vs0, 2);
        vd0 += __shfl_xor_sync(0xffffffffu, vd0, 1);
        vd0 += __shfl_xor_sync(0xffffffffu, vd0, 2);
        vs1 += __shfl_xor_sync(0xffffffffu, vs1, 1);
        vs1 += __shfl_xor_sync(0xffffffffu, vs1, 2);
        vd1 += __shfl_xor_sync(0xffffffffu, vd1, 1);
        vd1 += __shfl_xor_sync(0xffffffffu, vd1, 2);
        if (qq == 0) {
            float ba = g_bass[l], bd = g_bads[l];
            if (row0 < NN) { g_ssrc[row0] = vs0 + ba; g_sdst[row0] = vd0 + bd; }
            if (row0 + 8 < NN) { g_ssrc[row0 + 8] = vs1 + ba; g_sdst[row0 + 8] = vd1 + bd; }
        }
    }

    const bool st0 = (row0 < NN);
    const bool st1 = (row0 + 8 < NN);
#pragma unroll
    for (int nt = 0; nt < 16; nt++) {
        float2 bb = *reinterpret_cast<const float2*>(sBias + nt * 8 + qq * 2);
        float o0 = acc[nt][0] + bb.x, o1 = acc[nt][1] + bb.y;
        float o2 = acc[nt][2] + bb.x, o3 = acc[nt][3] + bb.y;
        if (do_relu) {
            o0 = fmaxf(o0, 0.f); o1 = fmaxf(o1, 0.f);
            o2 = fmaxf(o2, 0.f); o3 = fmaxf(o3, 0.f);
        }
        if (c_sel == 0) {
            if (st0)
                *reinterpret_cast<float2*>(g_ha + (size_t)row0 * HH + nt * 8 + qq * 2) =
                    make_float2(o0, o1);
            if (st1)
                *reinterpret_cast<float2*>(g_ha + (size_t)(row0 + 8) * HH + nt * 8 + qq * 2) =
                    make_float2(o2, o3);
        } else {
            if (st0)
                *reinterpret_cast<__half2*>(g_msgh + (size_t)row0 * HH + nt * 8 + qq * 2) =
                    __floats2half2_rn(o0, o1);
            if (st1)
                *reinterpret_cast<__half2*>(g_msgh + (size_t)(row0 + 8) * HH + nt * 8 + qq * 2) =
                    __floats2half2_rn(o2, o3);
        }
    }
}

// ---------------- fp32 GEMM for input projection (K=64, runs once) ----------------
__global__ __launch_bounds__(256, 2) void k_gemm(const float* __restrict__ A,
                                                 const float* __restrict__ W,
                                                 const float* __restrict__ bias,
                                                 int nrows, int K) {
    float* C = g_ha;
    __shared__ __align__(16) float As[128][33];
    __shared__ __align__(16) float Ws[32][128];

    int tid = threadIdx.x;
    int bm = blockIdx.x * 128;
    int tx = tid & 15;
    int ty = tid >> 4;
    int n0 = tx * 8;
    int m0 = ty * 8;

    float acc[8][8];
#pragma unroll
    for (int i = 0; i < 8; i++)
#pragma unroll
        for (int j = 0; j < 8; j++) acc[i][j] = 0.f;

    int nch = K >> 5;
    for (int ch = 0; ch < nch; ch++) {
        int k0 = ch * 32;
#pragma unroll
        for (int i = 0; i < 4; i++) {
            int idx = tid + i * 256;
            int m = idx >> 3;
            int kq = (idx & 7) * 4;
            float4 v = make_float4(0.f, 0.f, 0.f, 0.f);
            int gr = bm + m;
            if (gr < nrows)
                v = *reinterpret_cast<const float4*>(A + (size_t)gr * K + k0 + kq);
            As[m][kq] = v.x; As[m][kq + 1] = v.y; As[m][kq + 2] = v.z; As[m][kq + 3] = v.w;
        }
#pragma unroll
        for (int i = 0; i < 4; i++) {
            int idx = tid + i * 256;
            int n = idx >> 3;
            int kq = (idx & 7) * 4;
            float4 v = *reinterpret_cast<const float4*>(W + (size_t)n * K + k0 + kq);
            Ws[kq][n] = v.x; Ws[kq + 1][n] = v.y; Ws[kq + 2][n] = v.z; Ws[kq + 3][n] = v.w;
        }
        __syncthreads();
#pragma unroll 8
        for (int kk = 0; kk < 32; kk++) {
            float a[8];
#pragma unroll
            for (int i = 0; i < 8; i++) a[i] = As[m0 + i][kk];
            float4 b0 = *reinterpret_cast<const float4*>(&Ws[kk][n0]);
            float4 b1 = *reinterpret_cast<const float4*>(&Ws[kk][n0 + 4]);
#pragma unroll
            for (int i = 0; i < 8; i++) {
                acc[i][0] = fmaf(a[i], b0.x, acc[i][0]);
                acc[i][1] = fmaf(a[i], b0.y, acc[i][1]);
                acc[i][2] = fmaf(a[i], b0.z, acc[i][2]);
                acc[i][3] = fmaf(a[i], b0.w, acc[i][3]);
                acc[i][4] = fmaf(a[i], b1.x, acc[i][4]);
                acc[i][5] = fmaf(a[i], b1.y, acc[i][5]);
                acc[i][6] = fmaf(a[i], b1.z, acc[i][6]);
                acc[i][7] = fmaf(a[i], b1.w, acc[i][7]);
            }
        }
        __syncthreads();
    }

    float4 bv0 = *reinterpret_cast<const float4*>(bias + n0);
    float4 bv1 = *reinterpret_cast<const float4*>(bias + n0 + 4);
#pragma unroll
    for (int i = 0; i < 8; i++) {
        int gr = bm + m0 + i;
        if (gr >= nrows) continue;
        float4 o0, o1;
        o0.x = fmaxf(acc[i][0] + bv0.x, 0.f); o0.y = fmaxf(acc[i][1] + bv0.y, 0.f);
        o0.z = fmaxf(acc[i][2] + bv0.z, 0.f); o0.w = fmaxf(acc[i][3] + bv0.w, 0.f);
        o1.x = fmaxf(acc[i][4] + bv1.x, 0.f); o1.y = fmaxf(acc[i][5] + bv1.y, 0.f);
        o1.z = fmaxf(acc[i][6] + bv1.z, 0.f); o1.w = fmaxf(acc[i][7] + bv1.w, 0.f);
        float* cp = C + (size_t)gr * HH + n0;
        *reinterpret_cast<float4*>(cp) = o0;
        *reinterpret_cast<float4*>(cp + 4) = o1;
    }
}

// ---------------- gather-aggregate: warp per node, double-buffered 4-edge groups ----------------
__global__ void k_agg(int l) {
    int gw = (blockIdx.x * blockDim.x + threadIdx.x) >> 5;
    int lane = threadIdx.x & 31;
    if (gw >= NN) return;
    int beg = g_rowptr[gw];
    int end = g_rowptr[gw + 1];
    float sdn = g_sdst[gw];
    const uint4* __restrict__ ep = g_epack + (size_t)l * EE;
    const uint2* __restrict__ msg2 = reinterpret_cast<const uint2*>(g_msgh);
    float4 acc = make_float4(0.f, 0.f, 0.f, 0.f);
    int ngrp = (end - beg) >> 2;
    int p = beg;
    if (ngrp > 0) {
        uint4 r0 = ep[p], r1 = ep[p + 1], r2 = ep[p + 2], r3 = ep[p + 3];
        for (int g = 0; g < ngrp; g++) {
            uint4 n0, n1, n2, n3;
            bool more = (g + 1 < ngrp);
            if (more) {
                int q = p + 4;
                n0 = ep[q]; n1 = ep[q + 1]; n2 = ep[q + 2]; n3 = ep[q + 3];
            }
            float ss0 = g_ssrc[r0.x], ss1 = g_ssrc[r1.x];
            float ss2 = g_ssrc[r2.x], ss3 = g_ssrc[r3.x];
            uint2 m0 = msg2[(size_t)r0.x * 32 + lane];
            uint2 m1 = msg2[(size_t)r1.x * 32 + lane];
            uint2 m2 = msg2[(size_t)r2.x * 32 + lane];
            uint2 m3 = msg2[(size_t)r3.x * 32 + lane];
            float g0 = __uint_as_float(r0.y) /
                       (1.f + __expf(-(ss0 + sdn + __uint_as_float(r0.z))));
            float g1 = __uint_as_float(r1.y) /
                       (1.f + __expf(-(ss1 + sdn + __uint_as_float(r1.z))));
            float g2 = __uint_as_float(r2.y) /
                       (1.f + __expf(-(ss2 + sdn + __uint_as_float(r2.z))));
            float g3 = __uint_as_float(r3.y) /
                       (1.f + __expf(-(ss3 + sdn + __uint_as_float(r3.z))));
            float2 a0 = __half22float2(*reinterpret_cast<__half2*>(&m0.x));
            float2 b0 = __half22float2(*reinterpret_cast<__half2*>(&m0.y));
            float2 a1 = __half22float2(*reinterpret_cast<__half2*>(&m1.x));
            float2 b1 = __half22float2(*reinterpret_cast<__half2*>(&m1.y));
            float2 a2 = __half22float2(*reinterpret_cast<__half2*>(&m2.x));
            float2 b2 = __half22float2(*reinterpret_cast<__half2*>(&m2.y));
            float2 a3 = __half22float2(*reinterpret_cast<__half2*>(&m3.x));
            float2 b3 = __half22float2(*reinterpret_cast<__half2*>(&m3.y));
            acc.x = fmaf(a0.x, g0, acc.x); acc.y = fmaf(a0.y, g0, acc.y);
            acc.z = fmaf(b0.x, g0, acc.z); acc.w = fmaf(b0.y, g0, acc.w);
            acc.x = fmaf(a1.x, g1, acc.x); acc.y = fmaf(a1.y, g1, acc.y);
            acc.z = fmaf(b1.x, g1, acc.z); acc.w = fmaf(b1.y, g1, acc.w);
            acc.x = fmaf(a2.x, g2, acc.x); acc.y = fmaf(a2.y, g2, acc.y);
            acc.z = fmaf(b2.x, g2, acc.z); acc.w = fmaf(b2.y, g2, acc.w);
            acc.x = fmaf(a3.x, g3, acc.x); acc.y = fmaf(a3.y, g3, acc.y);
            acc.z = fmaf(b3.x, g3, acc.z); acc.w = fmaf(b3.y, g3, acc.w);
            if (more) { r0 = n0; r1 = n1; r2 = n2; r3 = n3; }
            p += 4;
        }
    }
    for (; p < end; p++) {
        uint4 r0 = ep[p];
        float ss0 = g_ssrc[r0.x];
        uint2 m0 = msg2[(size_t)r0.x * 32 + lane];
        float g0 = __uint_as_float(r0.y) /
                   (1.f + __expf(-(ss0 + sdn + __uint_as_float(r0.z))));
        float2 a0 = __half22float2(*reinterpret_cast<__half2*>(&m0.x));
        float2 b0 = __half22float2(*reinterpret_cast<__half2*>(&m0.y));
        acc.x = fmaf(a0.x, g0, acc.x); acc.y = fmaf(a0.y, g0, acc.y);
        acc.z = fmaf(b0.x, g0, acc.z); acc.w = fmaf(b0.y, g0, acc.w);
    }
    float4 h4 = reinterpret_cast<const float4*>(g_ha)[(size_t)gw * 32 + lane];
    float4 o;
    o.x = h4.x + acc.x; o.y = h4.y + acc.y; o.z = h4.z + acc.z; o.w = h4.w + acc.w;
    reinterpret_cast<float4*>(g_a2)[(size_t)gw * 32 + lane] = o;
}

// ---------------- graph readout ----------------
__global__ void k_grep() {
    int c = threadIdx.x & 127;
    int half = threadIdx.x >> 7;
    int rs = blockIdx.x * 196;
    int re = rs + 196;
    if (re > NN) re = NN;
    float acc = 0.f;
    for (int r = rs + half; r < re; r += 2) acc += g_ha[(size_t)r * HH + c];
    __shared__ float sr[256];
    sr[threadIdx.x] = acc;
    __syncthreads();
    if (threadIdx.x < 128)
        g_gpart[blockIdx.x * HH + threadIdx.x] = sr[threadIdx.x] + sr[threadIdx.x + 128];
}

__global__ void k_final(const float* __restrict__ W_out, const float* __restrict__ b_out,
                        float* __restrict__ out) {
    int t = threadIdx.x;  // 128 threads
    float s = 0.f;
    for (int b = 0; b < 256; b++) s += g_gpart[b * HH + t];
    float v = s * (1.f / (float)NN) * W_out[t];
    __shared__ float r[128];
    r[t] = v;
    __syncthreads();
    for (int off = 64; off; off >>= 1) {
        if (t < off) r[t] += r[t + off];
        __syncthreads();
    }
    if (t == 0) out[0] = (r[0] + b_out[0]) * (1.f / 50.f);
}

// ---------------- launch ----------------
extern "C" void kernel_launch(void* const* d_in, const int* in_sizes, int n_in,
                              void* d_out, int out_size) {
    const float* x      = (const float*)d_in[0];
    const int*   ei     = (const int*)d_in[1];
    const float* ew     = (const float*)d_in[2];
    const float* ea     = (const float*)d_in[3];
    const float* W_in   = (const float*)d_in[4];
    const float* b_in   = (const float*)d_in[5];
    const float* W_e1   = (const float*)d_in[6];
    const float* b_e1   = (const float*)d_in[7];
    const float* W_e2   = (const float*)d_in[8];
    const float* b_e2   = (const float*)d_in[9];
    const float* W_as   = (const float*)d_in[10];
    const float* b_as   = (const float*)d_in[11];
    const float* W_ad   = (const float*)d_in[12];
    const float* b_ad   = (const float*)d_in[13];
    const float* W_m    = (const float*)d_in[14];
    const float* b_m    = (const float*)d_in[15];
    const float* W_r    = (const float*)d_in[16];
    const float* b_r    = (const float*)d_in[17];
    const float* W_out  = (const float*)d_in[18];
    const float* b_out  = (const float*)d_in[19];
    float* out = (float*)d_out;

    cudaFuncSetAttribute(k_sbias_tc, cudaFuncAttributeMaxDynamicSharedMemorySize, SBT_SMEM);
    cudaFuncSetAttribute(k_gemm_tc, cudaFuncAttributeMaxDynamicSharedMemorySize, GT_SMEM);

    const int gridE = (EE + 255) / 256;   // 6250
    const int gridN = (NN + 255) / 256;   // 196
    const int gridG = (NN + 127) / 128;   // 391

    // Order chosen so the 4th launch (ncu capture slot) is the layer-0 msg tc-GEMM.
    k_prep<<<LL, HH>>>(W_e1, b_e1, W_e2, b_e2, W_as, b_as, W_ad, b_ad);
    k_prepW<<<12 * 128, 32>>>(W_m, W_r);
    k_gemm<<<gridG, 256>>>(x, W_in, b_in, NN, DIN);          // ha = relu(x@W_in^T+b)
    k_gemm_tc<<<gridG, 256, GT_SMEM>>>(1, 0, b_m, 1, 0, 1, 0);  // msg l=0 (4th launch)
    k_init<<<gridN, 256>>>();
    k_prepB<<<LL * 16, 32>>>();
    k_hist<<<gridE, 256>>>(ei);
    k_scanA<<<49, 1024>>>();
    k_scanB<<<1, 32>>>();
    k_scanC<<<49, 1024>>>();
    k_scatter<<<gridE, 256>>>(ei, ew);
    k_sbias_tc<<<625, 256, SBT_SMEM>>>(ea);   // writes g_epack for all layers

    for (int l = 0; l < LL; l++) {
        if (l > 0) {
            // msg = ha @ W_m^T + b_m (fp16 out, + fused s_src/s_dst scores)
            k_gemm_tc<<<gridG, 256, GT_SMEM>>>(1, l * 2 + 0, b_m + l * HH, 1, 0, 1, l);
        }
        // a2 = ha + segment_sum(msg[src] * gate)
        k_agg<<<gridE, 256>>>(l);
        // ha = relu(a2 @ W_r^T + b_r)
        k_gemm_tc<<<gridG, 256, GT_SMEM>>>(2, l * 2 + 1, b_r + l * HH, 0, 1, 0, l);
    }

    k_grep<<<256, 256>>>();
    k_final<<<1, 128>>>(W_out, b_out, out);
}

// round 17
// speedup vs baseline: 1.1037x; 1.1037x over previous
#include <cuda_runtime.h>
#include <cuda_bf16.h>
#include <cuda_fp16.h>
#include <math.h>
#include <stdint.h>

#define NN 50000
#define EE 1600000
#define HH 128
#define DIN 64
#define DE 16
#define LL 6

// ---------------- scratch (static __device__ globals; no allocation) ----------------
__device__ float g_ha[NN * HH];     // node features (always post-relu)
__device__ __half g_msgh[NN * HH];  // per-node message linear output (fp16)
__device__ float g_a2[NN * HH];     // ha + agg (input to update GEMM)
__device__ float g_ssrc[NN];
__device__ float g_sdst[NN];
__device__ float g_sb[(size_t)LL * EE];  // per-layer per-edge bias (CSR order)
__device__ int g_counts[NN];
__device__ int g_rowptr[NN + 1];
__device__ int g_cursor[NN];
__device__ int g_perm[EE];   // csr pos -> original edge id
__device__ int g_srcp[EE];   // csr-ordered src index
__device__ float g_ewp[EE];  // csr-ordered clipped edge weight
__device__ float g_w1p[LL * HH * DE];  // W_e1 * colsum(W_e2)  (SIGNED fold)
__device__ float g_b1p[LL * HH];       // b_e1 * colsum(W_e2)
__device__ float g_sgnF[LL * HH];      // sign(colsum(W_e2)) as +-1.0f
__device__ float g_cas[LL * HH];       // colsum(W_as)
__device__ float g_cad[LL * HH];       // colsum(W_ad)
__device__ float g_be2s[LL];
__device__ float g_bass[LL];
__device__ float g_bads[LL];
__device__ float g_gpart[256 * HH];
__device__ int g_bsum[49];
__device__ int g_boff[49];
// pre-packed B fragments for edge-MLP mma: [l][ntile][lane] -> {b0_hi, b1_hi, b0_lo, b1_lo}
__device__ __align__(16) uint4 g_Bfrag[LL * 16 * 32];
// pre-packed W fragments for node GEMMs: 12 matrices (l*2: W_m, l*2+1: W_r)
__device__ __align__(16) uint4 g_Wfrag[12 * 4096];

// ---------------- small helpers ----------------
__device__ __forceinline__ float tanh_fast(float x) {
    float y;
    asm("tanh.approx.f32 %0, %1;" : "=f"(y) : "f"(x));
    return y;
}
__device__ __forceinline__ unsigned pk2(float a, float b) {
    __nv_bfloat162 t = __floats2bfloat162_rn(a, b);
    return *reinterpret_cast<unsigned*>(&t);
}
__device__ __forceinline__ float hif(float a) {
    return __bfloat162float(__float2bfloat16(a));
}
__device__ __forceinline__ void mma16816(float& d0, float& d1, float& d2, float& d3,
                                         unsigned a0, unsigned a1, unsigned a2, unsigned a3,
                                         unsigned b0, unsigned b1,
                                         float c0, float c1, float c2, float c3) {
    asm volatile(
        "mma.sync.aligned.m16n8k16.row.col.f32.bf16.bf16.f32 "
        "{%0,%1,%2,%3}, {%4,%5,%6,%7}, {%8,%9}, {%10,%11,%12,%13};"
        : "=f"(d0), "=f"(d1), "=f"(d2), "=f"(d3)
        : "r"(a0), "r"(a1), "r"(a2), "r"(a3), "r"(b0), "r"(b1),
          "f"(c0), "f"(c1), "f"(c2), "f"(c3));
}

// ---------------- init: zero histogram counters ----------------
__global__ void k_init() {
    int i = blockIdx.x * blockDim.x + threadIdx.x;
    if (i < NN) g_counts[i] = 0;
}

// ---------------- precompute column sums / folded edge-MLP weights ----------------
__global__ void k_prep(const float* __restrict__ W_e1, const float* __restrict__ b_e1,
                       const float* __restrict__ W_e2, const float* __restrict__ b_e2,
                       const float* __restrict__ W_as, const float* __restrict__ b_as,
                       const float* __restrict__ W_ad, const float* __restrict__ b_ad) {
    int l = blockIdx.x;       // 0..5
    int t = threadIdx.x;      // 0..127
    const float* was = W_as + l * HH * HH;
    const float* wad = W_ad + l * HH * HH;
    const float* we2 = W_e2 + l * HH * HH;
    float sa = 0.f, sd = 0.f, s2 = 0.f;
    for (int j = 0; j < HH; j++) {
        sa += was[j * HH + t];
        sd += wad[j * HH + t];
        s2 += we2[j * HH + t];
    }
    g_cas[l * HH + t] = sa;
    g_cad[l * HH + t] = sd;
    g_b1p[l * HH + t] = b_e1[l * HH + t] * s2;
    g_sgnF[l * HH + t] = (s2 < 0.f) ? -1.f : 1.f;
    const float* we1 = W_e1 + (l * HH + t) * DE;
    float* w1p = g_w1p + (l * HH + t) * DE;
    for (int k = 0; k < DE; k++) w1p[k] = we1[k] * s2;
    if (t == 0) {
        float s = 0.f;
        for (int j = 0; j < HH; j++) s += b_e2[l * HH + j];
        g_be2s[l] = s;
        s = 0.f;
        for (int j = 0; j < HH; j++) s += b_as[l * HH + j];
        g_bass[l] = s;
        s = 0.f;
        for (int j = 0; j < HH; j++) s += b_ad[l * HH + j];
        g_bads[l] = s;
    }
}

// ---------------- pre-pack B fragments (edge MLP, K=16) ----------------
__global__ void k_prepB() {
    int l = blockIdx.x >> 4;
    int nt = blockIdx.x & 15;
    int lane = threadIdx.x;
    int n = nt * 8 + (lane >> 2);
    int k0 = (lane & 3) * 2;
    const float* w = g_w1p + (l * HH + n) * DE;
    float w0 = w[k0], w1 = w[k0 + 1], w8 = w[k0 + 8], w9 = w[k0 + 9];
    float h0 = hif(w0), h1 = hif(w1), h8 = hif(w8), h9 = hif(w9);
    uint4 f;
    f.x = pk2(h0, h1);
    f.y = pk2(h8, h9);
    f.z = pk2(w0 - h0, w1 - h1);
    f.w = pk2(w8 - h8, w9 - h9);
    g_Bfrag[(l * 16 + nt) * 32 + lane] = f;
}

// ---------------- pre-pack W fragments (node GEMMs, K=128) ----------------
__global__ void k_prepW(const float* __restrict__ Wm, const float* __restrict__ Wr) {
    int m = blockIdx.x >> 7;
    int rem = blockIdx.x & 127;
    int ks = rem >> 4;
    int nt = rem & 15;
    const float* W = (m & 1) ? (Wr + (m >> 1) * HH * HH) : (Wm + (m >> 1) * HH * HH);
    int lane = threadIdx.x;
    int n = nt * 8 + (lane >> 2);
    int k0 = ks * 16 + (lane & 3) * 2;
    float w0 = W[n * HH + k0], w1 = W[n * HH + k0 + 1];
    float w8 = W[n * HH + k0 + 8], w9 = W[n * HH + k0 + 9];
    float h0 = hif(w0), h1 = hif(w1), h8 = hif(w8), h9 = hif(w9);
    uint4 f;
    f.x = pk2(h0, h1);
    f.y = pk2(h8, h9);
    f.z = pk2(w0 - h0, w1 - h1);
    f.w = pk2(w8 - h8, w9 - h9);
    g_Wfrag[m * 4096 + (ks * 16 + nt) * 32 + lane] = f;
}

// ---------------- CSR build ----------------
__global__ void k_hist(const int* __restrict__ ei) {
    int e = blockIdx.x * blockDim.x + threadIdx.x;
    if (e < EE) atomicAdd(&g_counts[ei[EE + e]], 1);
}

__global__ void k_scanA() {
    __shared__ int sh[1024];
    int i = blockIdx.x * 1024 + threadIdx.x;
    int v = (i < NN) ? g_counts[i] : 0;
    sh[threadIdx.x] = v;
    __syncthreads();
    for (int off = 512; off > 0; off >>= 1) {
        if (threadIdx.x < off) sh[threadIdx.x] += sh[threadIdx.x + off];
        __syncthreads();
    }
    if (threadIdx.x == 0) g_bsum[blockIdx.x] = sh[0];
}
__global__ void k_scanB() {
    if (threadIdx.x == 0) {
        int r = 0;
        for (int b = 0; b < 49; b++) { g_boff[b] = r; r += g_bsum[b]; }
    }
}
__global__ void k_scanC() {
    __shared__ int sh[1024];
    int t = threadIdx.x;
    int i = blockIdx.x * 1024 + t;
    int v = (i < NN) ? g_counts[i] : 0;
    sh[t] = v;
    __syncthreads();
    for (int off = 1; off < 1024; off <<= 1) {
        int x = (t >= off) ? sh[t - off] : 0;
        __syncthreads();
        sh[t] += x;
        __syncthreads();
    }
    if (i < NN) {
        int excl = sh[t] - v + g_boff[blockIdx.x];
        g_rowptr[i] = excl;
        g_cursor[i] = excl;
        if (i == NN - 1) g_rowptr[NN] = excl + v;
    }
}

__global__ void k_scatter(const int* __restrict__ ei, const float* __restrict__ ew) {
    int e = blockIdx.x * blockDim.x + threadIdx.x;
    if (e >= EE) return;
    int d = ei[EE + e];
    int pos = atomicAdd(&g_cursor[d], 1);
    g_perm[pos] = e;
    g_srcp[pos] = ei[e];
    float w = ew[e];
    g_ewp[pos] = fminf(fmaxf(w, 0.f), 1.f);
}

// ---------------- per-edge bias for all 6 layers via mma.sync bf16 ----------------
#define SBT_SMEM (49152 + 3072 + 3072)
__global__ __launch_bounds__(256) void k_sbias_tc(const float* __restrict__ ea) {
    extern __shared__ char smem[];
    uint4* sF = reinterpret_cast<uint4*>(smem);
    float* sB = reinterpret_cast<float*>(smem + 49152);
    float* sS = reinterpret_cast<float*>(smem + 49152 + 3072);
    for (int i = threadIdx.x; i < 3072; i += 256) sF[i] = g_Bfrag[i];
    for (int i = threadIdx.x; i < 768; i += 256) {
        sB[i] = g_b1p[i];
        sS[i] = g_sgnF[i];
    }
    __syncthreads();

    const int wid = threadIdx.x >> 5;
    const int lane = threadIdx.x & 31;
    const int rA = lane >> 2;
    const int qq = lane & 3;

    for (int tile = blockIdx.x; tile < EE / 128; tile += gridDim.x) {
        const int p0 = tile * 128 + wid * 16;
        unsigned ah[4], al[4];
        {
            int e0 = g_perm[p0 + rA];
            int e1 = g_perm[p0 + rA + 8];
            const float2* r0 = reinterpret_cast<const float2*>(ea + (size_t)e0 * DE);
            const float2* r1 = reinterpret_cast<const float2*>(ea + (size_t)e1 * DE);
            float2 x0 = r0[qq], x2 = r0[qq + 4];
            float2 y0 = r1[qq], y2 = r1[qq + 4];
            x0.x = tanh_fast(x0.x); x0.y = tanh_fast(x0.y);
            x2.x = tanh_fast(x2.x); x2.y = tanh_fast(x2.y);
            y0.x = tanh_fast(y0.x); y0.y = tanh_fast(y0.y);
            y2.x = tanh_fast(y2.x); y2.y = tanh_fast(y2.y);
            float hx0 = hif(x0.x), hx1 = hif(x0.y);
            float hx8 = hif(x2.x), hx9 = hif(x2.y);
            float hy0 = hif(y0.x), hy1 = hif(y0.y);
            float hy8 = hif(y2.x), hy9 = hif(y2.y);
            ah[0] = pk2(hx0, hx1);
            ah[1] = pk2(hy0, hy1);
            ah[2] = pk2(hx8, hx9);
            ah[3] = pk2(hy8, hy9);
            al[0] = pk2(x0.x - hx0, x0.y - hx1);
            al[1] = pk2(y0.x - hy0, y0.y - hy1);
            al[2] = pk2(x2.x - hx8, x2.y - hx9);
            al[3] = pk2(y2.x - hy8, y2.y - hy9);
        }
#pragma unroll 1
        for (int l = 0; l < LL; l++) {
            const float* bl = sB + l * HH;
            const float* sl = sS + l * HH;
            float accA = 0.f, accB = 0.f;
#pragma unroll
            for (int nt = 0; nt < 16; nt++) {
                uint4 bf = sF[(l * 16 + nt) * 32 + lane];
                float2 bb = *reinterpret_cast<const float2*>(bl + nt * 8 + qq * 2);
                float d0 = bb.x, d1 = bb.y, d2 = bb.x, d3 = bb.y;
                mma16816(d0, d1, d2, d3, ah[0], ah[1], ah[2], ah[3], bf.x, bf.y,
                         d0, d1, d2, d3);
                mma16816(d0, d1, d2, d3, al[0], al[1], al[2], al[3], bf.x, bf.y,
                         d0, d1, d2, d3);
                mma16816(d0, d1, d2, d3, ah[0], ah[1], ah[2], ah[3], bf.z, bf.w,
                         d0, d1, d2, d3);
                float2 ss = *reinterpret_cast<const float2*>(sl + nt * 8 + qq * 2);
                accA = fmaf(fmaxf(d0 * ss.x, 0.f), ss.x, accA);
                accA = fmaf(fmaxf(d1 * ss.y, 0.f), ss.y, accA);
                accB = fmaf(fmaxf(d2 * ss.x, 0.f), ss.x, accB);
                accB = fmaf(fmaxf(d3 * ss.y, 0.f), ss.y, accB);
            }
            accA += __shfl_xor_sync(0xffffffffu, accA, 1);
            accA += __shfl_xor_sync(0xffffffffu, accA, 2);
            accB += __shfl_xor_sync(0xffffffffu, accB, 1);
            accB += __shfl_xor_sync(0xffffffffu, accB, 2);
            if (qq == 0) {
                float c = g_be2s[l];
                g_sb[(size_t)l * EE + p0 + rA] = accA + c;
                g_sb[(size_t)l * EE + p0 + rA + 8] = accB + c;
            }
        }
    }
}

// ---------------- tensor-core node GEMM, N-split for occupancy ----------------
// Grid (391, 2): blockIdx.y selects output columns [ny*64, ny*64+64).
// Each warp: 16 rows x 64 cols -> 32 accumulator regs/thread.
#define GT_SMEM (32768 + 256 + 1024)
__global__ __launch_bounds__(256) void k_gemm_tc(int a_sel, int mat,
                                                 const float* __restrict__ bias,
                                                 int c_sel, int do_relu,
                                                 int do_scores, int l) {
    extern __shared__ char smem[];
    uint4* sW = reinterpret_cast<uint4*>(smem);                    // 2048 uint4 = 32KB
    float* sBias = reinterpret_cast<float*>(smem + 32768);         // 64
    float* sCas = reinterpret_cast<float*>(smem + 32768 + 256);    // 128
    float* sCad = sCas + 128;                                      // 128

    const int ny = blockIdx.y;
    const float* A = (a_sel == 1) ? g_ha : g_a2;
    const uint4* Wf = g_Wfrag + (size_t)mat * 4096;

    // load this half's fragments: nt_local 0..7 -> global nt = ny*8 + nt_local
    for (int i = threadIdx.x; i < 2048; i += 256) {
        int ks = i >> 8;
        int rem = i & 255;
        int ntl = rem >> 5;
        int ln = rem & 31;
        sW[i] = Wf[ks * 512 + (ny * 8 + ntl) * 32 + ln];
    }
    if (threadIdx.x < 64) sBias[threadIdx.x] = bias[ny * 64 + threadIdx.x];
    const int scores_here = do_scores && (ny == 0);
    if (scores_here && threadIdx.x < 128) {
        sCas[threadIdx.x] = g_cas[l * HH + threadIdx.x];
        sCad[threadIdx.x] = g_cad[l * HH + threadIdx.x];
    }
    __syncthreads();

    const int wid = threadIdx.x >> 5;
    const int lane = threadIdx.x & 31;
    const int rA = lane >> 2;
    const int qq = lane & 3;

    const int row0 = blockIdx.x * 128 + wid * 16 + rA;
    const int r0 = (row0 < NN) ? row0 : (NN - 1);
    const int r1 = (row0 + 8 < NN) ? (row0 + 8) : (NN - 1);

    float acc[8][4];
#pragma unroll
    for (int nt = 0; nt < 8; nt++)
#pragma unroll
        for (int j = 0; j < 4; j++) acc[nt][j] = 0.f;

    float vs0 = 0.f, vd0 = 0.f, vs1 = 0.f, vd1 = 0.f;

#pragma unroll 1
    for (int ks = 0; ks < 8; ks++) {
        const float* ar0 = A + (size_t)r0 * HH + ks * 16;
        const float* ar1 = A + (size_t)r1 * HH + ks * 16;
        float2 x0 = *reinterpret_cast<const float2*>(ar0 + qq * 2);
        float2 x8 = *reinterpret_cast<const float2*>(ar0 + qq * 2 + 8);
        float2 y0 = *reinterpret_cast<const float2*>(ar1 + qq * 2);
        float2 y8 = *reinterpret_cast<const float2*>(ar1 + qq * 2 + 8);
        if (scores_here) {
            int c0 = ks * 16 + qq * 2;
            vs0 += x0.x * sCas[c0] + x0.y * sCas[c0 + 1]
                 + x8.x * sCas[c0 + 8] + x8.y * sCas[c0 + 9];
            vd0 += x0.x * sCad[c0] + x0.y * sCad[c0 + 1]
                 + x8.x * sCad[c0 + 8] + x8.y * sCad[c0 + 9];
            vs1 += y0.x * sCas[c0] + y0.y * sCas[c0 + 1]
                 + y8.x * sCas[c0 + 8] + y8.y * sCas[c0 + 9];
            vd1 += y0.x * sCad[c0] + y0.y * sCad[c0 + 1]
                 + y8.x * sCad[c0 + 8] + y8.y * sCad[c0 + 9];
        }
        float hx0 = hif(x0.x), hx1 = hif(x0.y), hx8 = hif(x8.x), hx9 = hif(x8.y);
        float hy0 = hif(y0.x), hy1 = hif(y0.y), hy8 = hif(y8.x), hy9 = hif(y8.y);
        unsigned ah0 = pk2(hx0, hx1), ah1 = pk2(hy0, hy1);
        unsigned ah2 = pk2(hx8, hx9), ah3 = pk2(hy8, hy9);
        unsigned al0 = pk2(x0.x - hx0, x0.y - hx1);
        unsigned al1 = pk2(y0.x - hy0, y0.y - hy1);
        unsigned al2 = pk2(x8.x - hx8, x8.y - hx9);
        unsigned al3 = pk2(y8.x - hy8, y8.y - hy9);
        const uint4* wrow = sW + ks * 256 + lane;
#pragma unroll
        for (int nt = 0; nt < 8; nt++) {
            uint4 bf = wrow[nt * 32];
            mma16816(acc[nt][0], acc[nt][1], acc[nt][2], acc[nt][3],
                     ah0, ah1, ah2, ah3, bf.x, bf.y,
                     acc[nt][0], acc[nt][1], acc[nt][2], acc[nt][3]);
            mma16816(acc[nt][0], acc[nt][1], acc[nt][2], acc[nt][3],
                     al0, al1, al2, al3, bf.x, bf.y,
                     acc[nt][0], acc[nt][1], acc[nt][2], acc[nt][3]);
            mma16816(acc[nt][0], acc[nt][1], acc[nt][2], acc[nt][3],
                     ah0, ah1, ah2, ah3, bf.z, bf.w,
                     acc[nt][0], acc[nt][1], acc[nt][2], acc[nt][3]);
        }
    }

    if (scores_here) {
        vs0 += __shfl_xor_sync(0xffffffffu, vs0, 1);
        vs0 += __shfl_xor_sync(0xffffffffu, vs0, 2);
        vd0 += __shfl_xor_sync(0xffffffffu, vd0, 1);
        vd0 += __shfl_xor_sync(0xffffffffu, vd0, 2);
        vs1 += __shfl_xor_sync(0xffffffffu, vs1, 1);
        vs1 += __shfl_xor_sync(0xffffffffu, vs1, 2);
        vd1 += __shfl_xor_sync(0xffffffffu, vd1, 1);
        vd1 += __shfl_xor_sync(0xffffffffu, vd1, 2);
        if (qq == 0) {
            float ba = g_bass[l], bd = g_bads[l];
            if (row0 < NN) { g_ssrc[row0] = vs0 + ba; g_sdst[row0] = vd0 + bd; }
            if (row0 + 8 < NN) { g_ssrc[row0 + 8] = vs1 + ba; g_sdst[row0 + 8] = vd1 + bd; }
        }
    }

    const bool st0 = (row0 < NN);
    const bool st1 = (row0 + 8 < NN);
    const int cbase = ny * 64;
#pragma unroll
    for (int nt = 0; nt < 8; nt++) {
        float2 bb = *reinterpret_cast<const float2*>(sBias + nt * 8 + qq * 2);
        float o0 = acc[nt][0] + bb.x, o1 = acc[nt][1] + bb.y;
        float o2 = acc[nt][2] + bb.x, o3 = acc[nt][3] + bb.y;
        if (do_relu) {
            o0 = fmaxf(o0, 0.f); o1 = fmaxf(o1, 0.f);
            o2 = fmaxf(o2, 0.f); o3 = fmaxf(o3, 0.f);
        }
        int coff = cbase + nt * 8 + qq * 2;
        if (c_sel == 0) {
            if (st0)
                *reinterpret_cast<float2*>(g_ha + (size_t)row0 * HH + coff) =
                    make_float2(o0, o1);
            if (st1)
                *reinterpret_cast<float2*>(g_ha + (size_t)(row0 + 8) * HH + coff) =
                    make_float2(o2, o3);
        } else {
            if (st0)
                *reinterpret_cast<__half2*>(g_msgh + (size_t)row0 * HH + coff) =
                    __floats2half2_rn(o0, o1);
            if (st1)
                *reinterpret_cast<__half2*>(g_msgh + (size_t)(row0 + 8) * HH + coff) =
                    __floats2half2_rn(o2, o3);
        }
    }
}

// ---------------- fp32 GEMM for input projection (K=64, runs once) ----------------
__global__ __launch_bounds__(256, 2) void k_gemm(const float* __restrict__ A,
                                                 const float* __restrict__ W,
                                                 const float* __restrict__ bias,
                                                 int nrows, int K) {
    float* C = g_ha;
    __shared__ __align__(16) float As[128][33];
    __shared__ __align__(16) float Ws[32][128];

    int tid = threadIdx.x;
    int bm = blockIdx.x * 128;
    int tx = tid & 15;
    int ty = tid >> 4;
    int n0 = tx * 8;
    int m0 = ty * 8;

    float acc[8][8];
#pragma unroll
    for (int i = 0; i < 8; i++)
#pragma unroll
        for (int j = 0; j < 8; j++) acc[i][j] = 0.f;

    int nch = K >> 5;
    for (int ch = 0; ch < nch; ch++) {
        int k0 = ch * 32;
#pragma unroll
        for (int i = 0; i < 4; i++) {
            int idx = tid + i * 256;
            int m = idx >> 3;
            int kq = (idx & 7) * 4;
            float4 v = make_float4(0.f, 0.f, 0.f, 0.f);
            int gr = bm + m;
            if (gr < nrows)
                v = *reinterpret_cast<const float4*>(A + (size_t)gr * K + k0 + kq);
            As[m][kq] = v.x; As[m][kq + 1] = v.y; As[m][kq + 2] = v.z; As[m][kq + 3] = v.w;
        }
#pragma unroll
        for (int i = 0; i < 4; i++) {
            int idx = tid + i * 256;
            int n = idx >> 3;
            int kq = (idx & 7) * 4;
            float4 v = *reinterpret_cast<const float4*>(W + (size_t)n * K + k0 + kq);
            Ws[kq][n] = v.x; Ws[kq + 1][n] = v.y; Ws[kq + 2][n] = v.z; Ws[kq + 3][n] = v.w;
        }
        __syncthreads();
#pragma unroll 8
        for (int kk = 0; kk < 32; kk++) {
            float a[8];
#pragma unroll
            for (int i = 0; i < 8; i++) a[i] = As[m0 + i][kk];
            float4 b0 = *reinterpret_cast<const float4*>(&Ws[kk][n0]);
            float4 b1 = *reinterpret_cast<const float4*>(&Ws[kk][n0 + 4]);
#pragma unroll
            for (int i = 0; i < 8; i++) {
                acc[i][0] = fmaf(a[i], b0.x, acc[i][0]);
                acc[i][1] = fmaf(a[i], b0.y, acc[i][1]);
                acc[i][2] = fmaf(a[i], b0.z, acc[i][2]);
                acc[i][3] = fmaf(a[i], b0.w, acc[i][3]);
                acc[i][4] = fmaf(a[i], b1.x, acc[i][4]);
                acc[i][5] = fmaf(a[i], b1.y, acc[i][5]);
                acc[i][6] = fmaf(a[i], b1.z, acc[i][6]);
                acc[i][7] = fmaf(a[i], b1.w, acc[i][7]);
            }
        }
        __syncthreads();
    }

    float4 bv0 = *reinterpret_cast<const float4*>(bias + n0);
    float4 bv1 = *reinterpret_cast<const float4*>(bias + n0 + 4);
#pragma unroll
    for (int i = 0; i < 8; i++) {
        int gr = bm + m0 + i;
        if (gr >= nrows) continue;
        float4 o0, o1;
        o0.x = fmaxf(acc[i][0] + bv0.x, 0.f); o0.y = fmaxf(acc[i][1] + bv0.y, 0.f);
        o0.z = fmaxf(acc[i][2] + bv0.z, 0.f); o0.w = fmaxf(acc[i][3] + bv0.w, 0.f);
        o1.x = fmaxf(acc[i][4] + bv1.x, 0.f); o1.y = fmaxf(acc[i][5] + bv1.y, 0.f);
        o1.z = fmaxf(acc[i][6] + bv1.z, 0.f); o1.w = fmaxf(acc[i][7] + bv1.w, 0.f);
        float* cp = C + (size_t)gr * HH + n0;
        *reinterpret_cast<float4*>(cp) = o0;
        *reinterpret_cast<float4*>(cp + 4) = o1;
    }
}

// ---------------- gather-aggregate: warp per destination node over CSR ----------------
__global__ void k_agg(int l) {
    int gw = (blockIdx.x * blockDim.x + threadIdx.x) >> 5;
    int lane = threadIdx.x & 31;
    if (gw >= NN) return;
    int beg = g_rowptr[gw];
    int end = g_rowptr[gw + 1];
    float sdn = g_sdst[gw];
    const float* __restrict__ sb = g_sb + (size_t)l * EE;
    const uint2* __restrict__ msg2 = reinterpret_cast<const uint2*>(g_msgh);
    float4 acc = make_float4(0.f, 0.f, 0.f, 0.f);
    int p = beg;
    for (; p + 1 < end; p += 2) {
        int s0 = g_srcp[p];
        int s1 = g_srcp[p + 1];
        float x0 = g_ssrc[s0] + sdn + sb[p];
        float x1 = g_ssrc[s1] + sdn + sb[p + 1];
        float gt0 = g_ewp[p] / (1.f + __expf(-x0));
        float gt1 = g_ewp[p + 1] / (1.f + __expf(-x1));
        uint2 m0 = msg2[(size_t)s0 * 32 + lane];
        uint2 m1 = msg2[(size_t)s1 * 32 + lane];
        float2 f0a = __half22float2(*reinterpret_cast<__half2*>(&m0.x));
        float2 f0b = __half22float2(*reinterpret_cast<__half2*>(&m0.y));
        float2 f1a = __half22float2(*reinterpret_cast<__half2*>(&m1.x));
        float2 f1b = __half22float2(*reinterpret_cast<__half2*>(&m1.y));
        acc.x = fmaf(f0a.x, gt0, acc.x); acc.y = fmaf(f0a.y, gt0, acc.y);
        acc.z = fmaf(f0b.x, gt0, acc.z); acc.w = fmaf(f0b.y, gt0, acc.w);
        acc.x = fmaf(f1a.x, gt1, acc.x); acc.y = fmaf(f1a.y, gt1, acc.y);
        acc.z = fmaf(f1b.x, gt1, acc.z); acc.w = fmaf(f1b.y, gt1, acc.w);
    }
    if (p < end) {
        int s0 = g_srcp[p];
        float x0 = g_ssrc[s0] + sdn + sb[p];
        float gt0 = g_ewp[p] / (1.f + __expf(-x0));
        uint2 m0 = msg2[(size_t)s0 * 32 + lane];
        float2 f0a = __half22float2(*reinterpret_cast<__half2*>(&m0.x));
        float2 f0b = __half22float2(*reinterpret_cast<__half2*>(&m0.y));
        acc.x = fmaf(f0a.x, gt0, acc.x); acc.y = fmaf(f0a.y, gt0, acc.y);
        acc.z = fmaf(f0b.x, gt0, acc.z); acc.w = fmaf(f0b.y, gt0, acc.w);
    }
    float4 h4 = reinterpret_cast<const float4*>(g_ha)[(size_t)gw * 32 + lane];
    float4 o;
    o.x = h4.x + acc.x; o.y = h4.y + acc.y; o.z = h4.z + acc.z; o.w = h4.w + acc.w;
    reinterpret_cast<float4*>(g_a2)[(size_t)gw * 32 + lane] = o;
}

// ---------------- graph readout ----------------
__global__ void k_grep() {
    int c = threadIdx.x & 127;
    int half = threadIdx.x >> 7;
    int rs = blockIdx.x * 196;
    int re = rs + 196;
    if (re > NN) re = NN;
    float acc = 0.f;
    for (int r = rs + half; r < re; r += 2) acc += g_ha[(size_t)r * HH + c];
    __shared__ float sr[256];
    sr[threadIdx.x] = acc;
    __syncthreads();
    if (threadIdx.x < 128)
        g_gpart[blockIdx.x * HH + threadIdx.x] = sr[threadIdx.x] + sr[threadIdx.x + 128];
}

__global__ void k_final(const float* __restrict__ W_out, const float* __restrict__ b_out,
                        float* __restrict__ out) {
    int t = threadIdx.x;  // 128 threads
    float s = 0.f;
    for (int b = 0; b < 256; b++) s += g_gpart[b * HH + t];
    float v = s * (1.f / (float)NN) * W_out[t];
    __shared__ float r[128];
    r[t] = v;
    __syncthreads();
    for (int off = 64; off; off >>= 1) {
        if (t < off) r[t] += r[t + off];
        __syncthreads();
    }
    if (t == 0) out[0] = (r[0] + b_out[0]) * (1.f / 50.f);
}

// ---------------- launch ----------------
extern "C" void kernel_launch(void* const* d_in, const int* in_sizes, int n_in,
                              void* d_out, int out_size) {
    const float* x      = (const float*)d_in[0];
    const int*   ei     = (const int*)d_in[1];
    const float* ew     = (const float*)d_in[2];
    const float* ea     = (const float*)d_in[3];
    const float* W_in   = (const float*)d_in[4];
    const float* b_in   = (const float*)d_in[5];
    const float* W_e1   = (const float*)d_in[6];
    const float* b_e1   = (const float*)d_in[7];
    const float* W_e2   = (const float*)d_in[8];
    const float* b_e2   = (const float*)d_in[9];
    const float* W_as   = (const float*)d_in[10];
    const float* b_as   = (const float*)d_in[11];
    const float* W_ad   = (const float*)d_in[12];
    const float* b_ad   = (const float*)d_in[13];
    const float* W_m    = (const float*)d_in[14];
    const float* b_m    = (const float*)d_in[15];
    const float* W_r    = (const float*)d_in[16];
    const float* b_r    = (const float*)d_in[17];
    const float* W_out  = (const float*)d_in[18];
    const float* b_out  = (const float*)d_in[19];
    float* out = (float*)d_out;

    cudaFuncSetAttribute(k_sbias_tc, cudaFuncAttributeMaxDynamicSharedMemorySize, SBT_SMEM);
    cudaFuncSetAttribute(k_gemm_tc, cudaFuncAttributeMaxDynamicSharedMemorySize, GT_SMEM);

    const int gridE = (EE + 255) / 256;   // 6250
    const int gridN = (NN + 255) / 256;   // 196
    const int gridG = (NN + 127) / 128;   // 391
    const dim3 gridT(gridG, 2);

    // Order chosen so the 4th launch (ncu capture slot) is the layer-0 msg tc-GEMM.
    k_prep<<<LL, HH>>>(W_e1, b_e1, W_e2, b_e2, W_as, b_as, W_ad, b_ad);
    k_prepW<<<12 * 128, 32>>>(W_m, W_r);
    k_gemm<<<gridG, 256>>>(x, W_in, b_in, NN, DIN);          // ha = relu(x@W_in^T+b)
    k_gemm_tc<<<gridT, 256, GT_SMEM>>>(1, 0, b_m, 1, 0, 1, 0);  // msg l=0 (4th launch)
    k_init<<<gridN, 256>>>();
    k_prepB<<<LL * 16, 32>>>();
    k_hist<<<gridE, 256>>>(ei);
    k_scanA<<<49, 1024>>>();
    k_scanB<<<1, 32>>>();
    k_scanC<<<49, 1024>>>();
    k_scatter<<<gridE, 256>>>(ei, ew);
    k_sbias_tc<<<625, 256, SBT_SMEM>>>(ea);

    for (int l = 0; l < LL; l++) {
        if (l > 0) {
            // msg = ha @ W_m^T + b_m (fp16 out, + fused s_src/s_dst scores)
            k_gemm_tc<<<gridT, 256, GT_SMEM>>>(1, l * 2 + 0, b_m + l * HH, 1, 0, 1, l);
        }
        // a2 = ha + segment_sum(msg[src] * gate)
        k_agg<<<gridE, 256>>>(l);
        // ha = relu(a2 @ W_r^T + b_r)
        k_gemm_tc<<<gridT, 256, GT_SMEM>>>(2, l * 2 + 1, b_r + l * HH, 0, 1, 0, l);
    }

    k_grep<<<256, 256>>>();
    k_final<<<1, 128>>>(W_out, b_out, out);
}